// round 7
// baseline (speedup 1.0000x reference)
#include <cuda_runtime.h>
#include <math.h>
#include <stdint.h>

// ---------------- problem constants ----------------
#define NTOK   16384        // 4 * 4096
#define DIM    1024
#define HID    2048
#define HV2    4096         // 2*HID
#define QK     128
#define G      256
#define NGRP   64           // 4 batches * 16 groups
#define NB     4
#define NGPB   16
#define LN_EPS 1e-5f

// ---------------- scratch (device globals) ----------------
__device__ float g_normed[(size_t)NTOK * DIM];
__device__ float g_vT    [(size_t)NGRP * HID * G];   // v transposed per group: [g][e][t]
__device__ float g_gate  [(size_t)NTOK * HID];
__device__ float g_qk    [(size_t)NTOK * QK];
__device__ float g_qq    [(size_t)NTOK * QK];        // [g][t][d]
__device__ float g_lq    [(size_t)NTOK * QK];
__device__ float g_qkh   [(size_t)NTOK * QK];
__device__ float g_lkT   [(size_t)NGRP * QK * G];    // lin_k transposed: [g][d][t]
__device__ float g_attn  [(size_t)NGRP * G * G];
__device__ float g_ao    [(size_t)NTOK * HID];
__device__ float g_linkv [(size_t)NGRP * HID * QK];  // [g][e][d]
__device__ float g_WhT   [(size_t)HV2 * DIM];
__device__ float g_WqkT  [(size_t)QK * DIM];
__device__ float g_WoutT [(size_t)DIM * HID];

__device__ __forceinline__ float silu(float x) { return x / (1.0f + expf(-x)); }
// round-to-nearest tf32 (removes HMMA truncation bias)
__device__ __forceinline__ float rtf(float f) {
    uint32_t u;
    asm("cvt.rna.tf32.f32 %0, %1;" : "=r"(u) : "f"(f));
    return __uint_as_float(u);
}

// ---------------- LayerNorm (float4, tf32-rounded output) ----------------
__global__ void __launch_bounds__(256) ln_kernel(const float* __restrict__ x,
                                                 const float* __restrict__ w,
                                                 const float* __restrict__ b) {
    int row = blockIdx.x;
    const float4* xr = (const float4*)(x + (size_t)row * DIM);
    float4 v = xr[threadIdx.x];
    float s  = v.x + v.y + v.z + v.w;
    float s2 = v.x * v.x + v.y * v.y + v.z * v.z + v.w * v.w;
    __shared__ float sh[8], sh2[8], rmu, rinv;
    for (int o = 16; o > 0; o >>= 1) {
        s  += __shfl_down_sync(0xffffffffu, s, o);
        s2 += __shfl_down_sync(0xffffffffu, s2, o);
    }
    int wid = threadIdx.x >> 5, lane = threadIdx.x & 31;
    if (lane == 0) { sh[wid] = s; sh2[wid] = s2; }
    __syncthreads();
    if (threadIdx.x == 0) {
        float a = 0.f, a2 = 0.f;
#pragma unroll
        for (int i = 0; i < 8; i++) { a += sh[i]; a2 += sh2[i]; }
        float mu  = a * (1.0f / DIM);
        float var = a2 * (1.0f / DIM) - mu * mu;
        rmu = mu; rinv = rsqrtf(var + LN_EPS);
    }
    __syncthreads();
    float mu = rmu, inv = rinv;
    float4 wv = ((const float4*)w)[threadIdx.x];
    float4 bv = ((const float4*)b)[threadIdx.x];
    float4 o;
    o.x = rtf((v.x - mu) * inv * wv.x + bv.x);
    o.y = rtf((v.y - mu) * inv * wv.y + bv.y);
    o.z = rtf((v.z - mu) * inv * wv.z + bv.z);
    o.w = rtf((v.w - mu) * inv * wv.w + bv.w);
    ((float4*)(g_normed + (size_t)row * DIM))[threadIdx.x] = o;
}

// ---------------- tiled transpose + tf32 rounding: in[R][C] -> out[C][R] ----------------
__global__ void transpose_k(const float* __restrict__ in, float* __restrict__ out,
                            int R, int C) {
    __shared__ float t[32][33];
    int c0 = blockIdx.x * 32, r0 = blockIdx.y * 32;
    int x = threadIdx.x, y = threadIdx.y;
#pragma unroll
    for (int j = 0; j < 32; j += 8)
        t[y + j][x] = in[(size_t)(r0 + y + j) * C + c0 + x];
    __syncthreads();
#pragma unroll
    for (int j = 0; j < 32; j += 8)
        out[(size_t)(c0 + y + j) * R + r0 + x] = rtf(t[x][y + j]);
}

// ---------------- heads: qk -> qq, qkh (fp32, FFMA consumer) + lq, lkT (tf32) ----------------
__global__ void __launch_bounds__(256) heads_kernel(const float* __restrict__ qk_w,
                                                    const float* __restrict__ qk_b) {
    __shared__ float sm[128][65];
    int t0 = blockIdx.x * 64;
#pragma unroll 4
    for (int i = 0; i < 32; ++i) {
        int idx = threadIdx.x + i * 256;        // 64*128
        int tl = idx >> 7, d = idx & 127;
        int tok = t0 + tl;
        float v = g_qk[(size_t)tok * QK + d];
        g_qq [(size_t)tok * QK + d] = v * qk_w[d]           + qk_b[d];
        g_lq [(size_t)tok * QK + d] = rtf(v * qk_w[QK + d]  + qk_b[QK + d]);
        g_qkh[(size_t)tok * QK + d] = v * qk_w[2 * QK + d]  + qk_b[2 * QK + d];
        sm[d][tl] = rtf(v * qk_w[3 * QK + d] + qk_b[3 * QK + d]);
    }
    __syncthreads();
    int grp = t0 >> 8, tg0 = t0 & 255;
#pragma unroll 4
    for (int i = 0; i < 32; ++i) {
        int idx = threadIdx.x + i * 256;
        int d = idx >> 6, tl = idx & 63;
        g_lkT[((size_t)grp * QK + d) * G + tg0 + tl] = sm[d][tl];
    }
}

// ---------------- sim / bias / relu^2 / mask (fp32 math, tf32-rounded output) ----------------
__global__ void __launch_bounds__(256) attn_kernel(const float* __restrict__ rel_table) {
    int z  = blockIdx.z;
    int m0 = blockIdx.y * 64, n0 = blockIdx.x * 64;
    const float* Q  = g_qq  + (size_t)z * G * QK;
    const float* Km = g_qkh + (size_t)z * G * QK;
    __shared__ float Qs[16][64];
    __shared__ float Ks[16][64];
    __shared__ float rt[32];
    int tid = threadIdx.x, tx = tid & 15, ty = tid >> 4;
    if (tid < 32) rt[tid] = rel_table[tid] * 11.313708498984761f;
    float acc[4][4] = {};
    for (int d0 = 0; d0 < QK; d0 += 16) {
        int row = tid >> 2, dc = (tid & 3) * 4;
        float4 q  = *(const float4*)&Q [(m0 + row) * QK + d0 + dc];
        float4 k4 = *(const float4*)&Km[(n0 + row) * QK + d0 + dc];
        Qs[dc + 0][row] = q.x;  Qs[dc + 1][row] = q.y;
        Qs[dc + 2][row] = q.z;  Qs[dc + 3][row] = q.w;
        Ks[dc + 0][row] = k4.x; Ks[dc + 1][row] = k4.y;
        Ks[dc + 2][row] = k4.z; Ks[dc + 3][row] = k4.w;
        __syncthreads();
#pragma unroll
        for (int kk = 0; kk < 16; kk++) {
            float ra[4], rb[4];
            *(float4*)ra = *(float4*)&Qs[kk][ty * 4];
            *(float4*)rb = *(float4*)&Ks[kk][tx * 4];
#pragma unroll
            for (int i = 0; i < 4; i++)
#pragma unroll
                for (int j = 0; j < 4; j++)
                    acc[i][j] += ra[i] * rb[j];
        }
        __syncthreads();
    }
    const float inv_lr = 0.48089834696298783f;
#pragma unroll
    for (int i = 0; i < 4; i++) {
        int gi = m0 + ty * 4 + i;
#pragma unroll
        for (int j = 0; j < 4; j++) {
            int gj = n0 + tx * 4 + j;
            float sim = acc[i][j] * (1.0f / G);
            int n = gi - gj;
            int bucket;
            if (n <= 0)      bucket = 0;
            else if (n < 16) bucket = n;
            else {
                bucket = 16 + (int)(logf((float)n * (1.0f / 16.0f)) * inv_lr * 16.0f);
                if (bucket > 31) bucket = 31;
            }
            sim += rt[bucket];
            float a = sim > 0.f ? sim * sim : 0.f;
            if (gj > gi) a = 0.f;
            g_attn[(size_t)z * (G * G) + gi * G + gj] = rtf(a);
        }
    }
}

// ---------------- exclusive group cumsum of lin_kv (tf32-rounded output) ----------------
__global__ void cumsum_kernel() {
    int p = blockIdx.x * blockDim.x + threadIdx.x;
    if (p >= NB * QK * HID) return;
    int b = p / (QK * HID);
    int off = p - b * (QK * HID);
    float acc = 0.f;
#pragma unroll
    for (int g = 0; g < NGPB; g++) {
        size_t idx = (size_t)(b * NGPB + g) * (QK * HID) + off;
        float t = g_linkv[idx];
        g_linkv[idx] = rtf(acc);
        acc += t;
    }
}

// ---------------- tf32 mma.sync GEMM, 128x128 CTA tile, K-chunk 32, 3-stage, LDSM ----------------
// D[m][n] = sum_k A[m][k]*B[n][k], both operands K-major (row.col for mma.sync)
#define STG     18432                       // one 128x32 operand stage (stride 36 floats)
#define NSTAGE  3
#define GEMM_SMEM (NSTAGE * 2 * STG)        // 110592 bytes (epilogue reuses first 68KB)

__device__ __forceinline__ uint32_t smem_u32(const void* p) {
    uint32_t a;
    asm("{ .reg .u64 t; cvta.to.shared.u64 t, %1; cvt.u32.u64 %0, t; }" : "=r"(a) : "l"(p));
    return a;
}
__device__ __forceinline__ void mma8(float* d, const uint32_t* a, const uint32_t* b) {
    asm volatile(
        "mma.sync.aligned.m16n8k8.row.col.f32.tf32.tf32.f32 "
        "{%0,%1,%2,%3}, {%4,%5,%6,%7}, {%8,%9}, {%0,%1,%2,%3};"
        : "+f"(d[0]), "+f"(d[1]), "+f"(d[2]), "+f"(d[3])
        : "r"(a[0]), "r"(a[1]), "r"(a[2]), "r"(a[3]), "r"(b[0]), "r"(b[1]));
}
__device__ __forceinline__ void ldsm4(uint32_t& r0, uint32_t& r1, uint32_t& r2, uint32_t& r3,
                                      uint32_t addr) {
    asm volatile("ldmatrix.sync.aligned.m8n8.x4.shared.b16 {%0,%1,%2,%3}, [%4];"
                 : "=r"(r0), "=r"(r1), "=r"(r2), "=r"(r3) : "r"(addr));
}

template <int CFG>
__global__ void __launch_bounds__(256, 2)
gemm_tc(const float* __restrict__ pbias, const float* __restrict__ paux,
        float* __restrict__ pout) {
    constexpr int K  = (CFG == 1 || CFG == 2) ? 1024
                     : (CFG == 3 || CFG == 4) ? 256
                     : (CFG == 5) ? 128 : 2048;
    constexpr int NC = K / 32;

    extern __shared__ char smem[];
    uint32_t sbase = smem_u32(smem);
    float* smf = (float*)smem;

    int tid = threadIdx.x, w = tid >> 5, lane = tid & 31;
    int grpL = lane >> 2, tig = lane & 3;
    int wm = w >> 2, wn = w & 3;            // 2 x 4 warp grid
    int z = blockIdx.z;
    int n0 = blockIdx.x * 128, m0 = blockIdx.y * 128;

    const float* A; const float* B;
    if      (CFG == 1) { A = g_normed;                     B = g_WhT;  }
    else if (CFG == 2) { A = g_normed;                     B = g_WqkT; }
    else if (CFG == 3) { A = g_attn + (size_t)z * G * G;   B = g_vT + (size_t)z * HID * G; }
    else if (CFG == 4) { A = g_vT + (size_t)z * HID * G;   B = g_lkT + (size_t)z * QK * G; }
    else if (CFG == 5) { A = g_lq + (size_t)z * G * QK;    B = g_linkv + (size_t)z * HID * QK; }
    else               { A = g_ao;                         B = g_WoutT; }

    float acc[4][4][4];
#pragma unroll
    for (int i = 0; i < 4; i++)
#pragma unroll
        for (int j = 0; j < 4; j++)
#pragma unroll
            for (int r = 0; r < 4; r++) acc[i][j][r] = 0.f;

    int ldr = tid >> 3, ldc = (tid & 7) * 4;          // global->smem mapping

    // ldmatrix lane-relative byte offsets (q = matrix id, rL = row within matrix)
    int q = lane >> 3, rL = lane & 7;
    uint32_t laneA = (uint32_t)(((wm * 64 + (q & 1) * 8 + rL) * 36 + (q >> 1) * 4) * 4);
    uint32_t laneB = (uint32_t)(((wn * 32 + (q >> 1) * 8 + rL) * 36 + (q & 1) * 4) * 4) + STG;

#define ISSUE_CHUNK(cc, st)                                                         \
    {                                                                               \
        const float* Ap = A + (size_t)m0 * K + (cc) * 32;                           \
        const float* Bp = B + (size_t)n0 * K + (cc) * 32;                           \
        uint32_t bb = sbase + (uint32_t)((st) * 2 * STG);                           \
        _Pragma("unroll")                                                           \
        for (int jj = 0; jj < 4; ++jj) {                                            \
            int r = ldr + jj * 32;                                                  \
            uint32_t da = bb + (uint32_t)((r * 36 + ldc) * 4);                      \
            asm volatile("cp.async.cg.shared.global [%0], [%1], 16;"                \
                         :: "r"(da), "l"(Ap + (size_t)r * K + ldc));                \
            asm volatile("cp.async.cg.shared.global [%0], [%1], 16;"                \
                         :: "r"(da + STG), "l"(Bp + (size_t)r * K + ldc));          \
        }                                                                           \
    }

    // prologue: stages 0,1
    ISSUE_CHUNK(0, 0);
    asm volatile("cp.async.commit_group;");
    ISSUE_CHUNK(1, 1);
    asm volatile("cp.async.commit_group;");

    for (int c = 0; c < NC; ++c) {
        int pf = c + 2;
        if (pf < NC) ISSUE_CHUNK(pf, pf % NSTAGE);
        asm volatile("cp.async.commit_group;");
        asm volatile("cp.async.wait_group 2;");
        __syncthreads();

        uint32_t abase = sbase + (uint32_t)((c % NSTAGE) * 2 * STG) + laneA;
        uint32_t bbase = sbase + (uint32_t)((c % NSTAGE) * 2 * STG) + laneB;
#pragma unroll
        for (int k8 = 0; k8 < 4; ++k8) {
            uint32_t af[4][4], bf[4][2];
#pragma unroll
            for (int i = 0; i < 4; ++i)
                ldsm4(af[i][0], af[i][1], af[i][2], af[i][3],
                      abase + (uint32_t)(i * 2304 + k8 * 32));
            ldsm4(bf[0][0], bf[0][1], bf[1][0], bf[1][1], bbase + (uint32_t)(k8 * 32));
            ldsm4(bf[2][0], bf[2][1], bf[3][0], bf[3][1],
                  bbase + (uint32_t)(2304 + k8 * 32));
#pragma unroll
            for (int i = 0; i < 4; ++i)
#pragma unroll
                for (int j = 0; j < 4; ++j)
                    mma8(acc[i][j], af[i], bf[j]);
        }
        __syncthreads();
    }
#undef ISSUE_CHUNK

    // ---- stage accumulators into smem [128][132] ----
#pragma unroll
    for (int i = 0; i < 4; ++i) {
#pragma unroll
        for (int j = 0; j < 4; ++j) {
            int row = wm * 64 + i * 16 + grpL;
            int col = wn * 32 + j * 8 + tig * 2;
            smf[row * 132 + col]           = acc[i][j][0];
            smf[row * 132 + col + 1]       = acc[i][j][1];
            smf[(row + 8) * 132 + col]     = acc[i][j][2];
            smf[(row + 8) * 132 + col + 1] = acc[i][j][3];
        }
    }
    __syncthreads();

    // ---- epilogue / global write ----
    if (CFG == 1 && n0 < HID) {
        // v branch: write transposed into g_vT[grp][gn][t] (tf32-rounded: GEMM operand)
        int grp = m0 >> 8, tg0 = m0 & 255;
#pragma unroll
        for (int it = 0; it < 16; ++it) {
            int cc = it * 8 + w;               // 0..127
            int gn = n0 + cc;
            float bias = pbias[gn];
            int t = lane * 4;
            float4 o;
            o.x = rtf(silu(smf[(t + 0) * 132 + cc] + bias));
            o.y = rtf(silu(smf[(t + 1) * 132 + cc] + bias));
            o.z = rtf(silu(smf[(t + 2) * 132 + cc] + bias));
            o.w = rtf(silu(smf[(t + 3) * 132 + cc] + bias));
            *(float4*)&g_vT[((size_t)grp * HID + gn) * G + tg0 + t] = o;
        }
        return;
    }
#pragma unroll
    for (int it = 0; it < 16; ++it) {
        int idx = tid + it * 256;              // 4096 float4 slots
        int r = idx >> 5, c4 = (idx & 31) * 4;
        int gm = m0 + r, gn = n0 + c4;
        float v0 = smf[r * 132 + c4 + 0];
        float v1 = smf[r * 132 + c4 + 1];
        float v2 = smf[r * 132 + c4 + 2];
        float v3 = smf[r * 132 + c4 + 3];
        if (CFG == 1) {                        // gate branch (n0 >= HID): fp32 consumer
            float4 o;
            o.x = silu(v0 + pbias[gn + 0]); o.y = silu(v1 + pbias[gn + 1]);
            o.z = silu(v2 + pbias[gn + 2]); o.w = silu(v3 + pbias[gn + 3]);
            *(float4*)&g_gate[(size_t)gm * HID + (gn - HID)] = o;
        } else if (CFG == 2) {                 // fp32 consumer (heads)
            float4 o;
            o.x = silu(v0 + pbias[gn + 0]); o.y = silu(v1 + pbias[gn + 1]);
            o.z = silu(v2 + pbias[gn + 2]); o.w = silu(v3 + pbias[gn + 3]);
            *(float4*)&g_qk[(size_t)gm * QK + gn] = o;
        } else if (CFG == 3) {                 // fp32 consumer (CFG5 epilogue)
            float4 o = make_float4(v0, v1, v2, v3);
            *(float4*)&g_ao[((size_t)z * G + gm) * HID + gn] = o;
        } else if (CFG == 4) {                 // cumsum rounds later
            float4 o = make_float4(v0 * (1.0f / G), v1 * (1.0f / G),
                                   v2 * (1.0f / G), v3 * (1.0f / G));
            *(float4*)&g_linkv[((size_t)z * HID + gm) * QK + gn] = o;
        } else if (CFG == 5) {                 // tf32-rounded: feeds CFG6 A
            size_t i0 = ((size_t)z * G + gm) * HID + gn;
            float4 qv = *(const float4*)&g_ao[i0];
            float4 gt = *(const float4*)&g_gate[i0];
            float4 o;
            o.x = rtf((qv.x + v0) * gt.x); o.y = rtf((qv.y + v1) * gt.y);
            o.z = rtf((qv.z + v2) * gt.z); o.w = rtf((qv.w + v3) * gt.w);
            *(float4*)&g_ao[i0] = o;
        } else {                               // CFG 6
            size_t i0 = (size_t)gm * DIM + gn;
            float4 xr = *(const float4*)&paux[i0];
            float4 o;
            o.x = v0 + pbias[gn + 0] + xr.x; o.y = v1 + pbias[gn + 1] + xr.y;
            o.z = v2 + pbias[gn + 2] + xr.z; o.w = v3 + pbias[gn + 3] + xr.w;
            *(float4*)&pout[i0] = o;
        }
    }
}

// ---------------- launch ----------------
extern "C" void kernel_launch(void* const* d_in, const int* in_sizes, int n_in,
                              void* d_out, int out_size) {
    const float* x    = (const float*)d_in[0];
    const float* ln_w = (const float*)d_in[1];
    const float* ln_b = (const float*)d_in[2];
    const float* Wh   = (const float*)d_in[3];
    const float* bh   = (const float*)d_in[4];
    const float* Wqk  = (const float*)d_in[5];
    const float* bqk  = (const float*)d_in[6];
    const float* qk_w = (const float*)d_in[7];
    const float* qk_b = (const float*)d_in[8];
    const float* rel  = (const float*)d_in[9];
    const float* Wout = (const float*)d_in[10];
    const float* bout = (const float*)d_in[11];
    float* out = (float*)d_out;

    cudaFuncSetAttribute(gemm_tc<1>, cudaFuncAttributeMaxDynamicSharedMemorySize, GEMM_SMEM);
    cudaFuncSetAttribute(gemm_tc<2>, cudaFuncAttributeMaxDynamicSharedMemorySize, GEMM_SMEM);
    cudaFuncSetAttribute(gemm_tc<3>, cudaFuncAttributeMaxDynamicSharedMemorySize, GEMM_SMEM);
    cudaFuncSetAttribute(gemm_tc<4>, cudaFuncAttributeMaxDynamicSharedMemorySize, GEMM_SMEM);
    cudaFuncSetAttribute(gemm_tc<5>, cudaFuncAttributeMaxDynamicSharedMemorySize, GEMM_SMEM);
    cudaFuncSetAttribute(gemm_tc<6>, cudaFuncAttributeMaxDynamicSharedMemorySize, GEMM_SMEM);

    float* WhT;   cudaGetSymbolAddress((void**)&WhT,   g_WhT);
    float* WqkT;  cudaGetSymbolAddress((void**)&WqkT,  g_WqkT);
    float* WoutT; cudaGetSymbolAddress((void**)&WoutT, g_WoutT);

    // weight transposes (K-major B operands, tf32-rounded)
    transpose_k<<<dim3(HV2 / 32, DIM / 32), dim3(32, 8)>>>(Wh,   WhT,   DIM, HV2);
    transpose_k<<<dim3(QK  / 32, DIM / 32), dim3(32, 8)>>>(Wqk,  WqkT,  DIM, QK);
    transpose_k<<<dim3(DIM / 32, HID / 32), dim3(32, 8)>>>(Wout, WoutT, HID, DIM);

    // 1) LayerNorm
    ln_kernel<<<NTOK, 256>>>(x, ln_w, ln_b);

    // 2) hv = silu(normed @ Wh + bh) -> vT (transposed) + gate
    gemm_tc<1><<<dim3(HV2 / 128, NTOK / 128, 1), 256, GEMM_SMEM>>>(bh, nullptr, nullptr);

    // 3) qk = silu(normed @ Wqk + bqk)
    gemm_tc<2><<<dim3(1, NTOK / 128, 1), 256, GEMM_SMEM>>>(bqk, nullptr, nullptr);

    // 4) heads (+ lin_k transpose)
    heads_kernel<<<NTOK / 64, 256>>>(qk_w, qk_b);

    // 5) attn scores
    attn_kernel<<<dim3(4, 4, NGRP), 256>>>(rel);

    // 6) quad_out = attn @ v
    gemm_tc<3><<<dim3(HID / 128, G / 128, NGRP), 256, GEMM_SMEM>>>(nullptr, nullptr, nullptr);

    // 7) lin_kv = v^T @ lin_k / g   -> [e][d]
    gemm_tc<4><<<dim3(1, HID / 128, NGRP), 256, GEMM_SMEM>>>(nullptr, nullptr, nullptr);

    // 8) exclusive group cumsum
    cumsum_kernel<<<(NB * QK * HID) / 256, 256>>>();

    // 9) lin_out = lin_q @ lin_kv ; ao = gate*(quad+lin)
    gemm_tc<5><<<dim3(HID / 128, G / 128, NGRP), 256, GEMM_SMEM>>>(nullptr, nullptr, nullptr);

    // 10) out = ao @ Wout + bout + x
    gemm_tc<6><<<dim3(DIM / 128, NTOK / 128, 1), 256, GEMM_SMEM>>>(bout, x, out);
}

// round 8
// speedup vs baseline: 1.0499x; 1.0499x over previous
#include <cuda_runtime.h>
#include <math.h>
#include <stdint.h>

// ---------------- problem constants ----------------
#define NTOK   16384        // 4 * 4096
#define DIM    1024
#define HID    2048
#define HV2    4096         // 2*HID
#define QK     128
#define G      256
#define NGRP   64           // 4 batches * 16 groups
#define NB     4
#define NGPB   16
#define LN_EPS 1e-5f

// ---------------- scratch (device globals) ----------------
__device__ float g_normed[(size_t)NTOK * DIM];
__device__ float g_vT    [(size_t)NGRP * HID * G];   // v transposed per group: [g][e][t]
__device__ float g_gate  [(size_t)NTOK * HID];
__device__ float g_qq    [(size_t)NTOK * QK];        // [g][t][d]
__device__ float g_lq    [(size_t)NTOK * QK];
__device__ float g_qkh   [(size_t)NTOK * QK];
__device__ float g_lkT   [(size_t)NGRP * QK * G];    // lin_k transposed: [g][d][t]
__device__ float g_attn  [(size_t)NGRP * G * G];
__device__ float g_ao    [(size_t)NTOK * HID];
__device__ float g_linkv [(size_t)NGRP * HID * QK];  // [g][e][d]
__device__ float g_WhT   [(size_t)HV2 * DIM];
__device__ float g_WqkT  [(size_t)QK * DIM];
__device__ float g_WoutT [(size_t)DIM * HID];

__device__ __forceinline__ float silu(float x) { return x / (1.0f + expf(-x)); }
// round-to-nearest tf32 (removes HMMA truncation bias)
__device__ __forceinline__ float rtf(float f) {
    uint32_t u;
    asm("cvt.rna.tf32.f32 %0, %1;" : "=r"(u) : "f"(f));
    return __uint_as_float(u);
}

// ---------------- LayerNorm (tf32-rounded output: GEMM operand) ----------------
__global__ void ln_kernel(const float* __restrict__ x,
                          const float* __restrict__ w,
                          const float* __restrict__ b) {
    int row = blockIdx.x;
    const float* xr = x + (size_t)row * DIM;
    float s = 0.f, s2 = 0.f;
    for (int i = threadIdx.x; i < DIM; i += blockDim.x) {
        float v = xr[i]; s += v; s2 += v * v;
    }
    __shared__ float sh[8], sh2[8];
    for (int o = 16; o > 0; o >>= 1) {
        s  += __shfl_down_sync(0xffffffffu, s, o);
        s2 += __shfl_down_sync(0xffffffffu, s2, o);
    }
    int wid = threadIdx.x >> 5, lane = threadIdx.x & 31;
    if (lane == 0) { sh[wid] = s; sh2[wid] = s2; }
    __syncthreads();
    if (threadIdx.x == 0) {
        float a = 0.f, a2 = 0.f;
        for (int i = 0; i < (int)(blockDim.x >> 5); i++) { a += sh[i]; a2 += sh2[i]; }
        sh[0] = a; sh2[0] = a2;
    }
    __syncthreads();
    float mu  = sh[0] * (1.0f / DIM);
    float var = sh2[0] * (1.0f / DIM) - mu * mu;
    float inv = rsqrtf(var + LN_EPS);
    float* o = g_normed + (size_t)row * DIM;
    for (int i = threadIdx.x; i < DIM; i += blockDim.x)
        o[i] = rtf((xr[i] - mu) * inv * w[i] + b[i]);
}

// ---------------- tiled transpose + tf32 rounding: in[R][C] -> out[C][R] ----------------
__global__ void transpose_k(const float* __restrict__ in, float* __restrict__ out,
                            int R, int C) {
    __shared__ float t[32][33];
    int c0 = blockIdx.x * 32, r0 = blockIdx.y * 32;
    int x = threadIdx.x, y = threadIdx.y;
#pragma unroll
    for (int j = 0; j < 32; j += 8)
        t[y + j][x] = in[(size_t)(r0 + y + j) * C + c0 + x];
    __syncthreads();
#pragma unroll
    for (int j = 0; j < 32; j += 8)
        out[(size_t)(c0 + y + j) * R + r0 + x] = rtf(t[x][y + j]);
}

// ---------------- sim / bias / relu^2 / mask (fp32 math, tf32-rounded output) ----------------
__global__ void __launch_bounds__(256) attn_kernel(const float* __restrict__ rel_table) {
    int z  = blockIdx.z;
    int m0 = blockIdx.y * 64, n0 = blockIdx.x * 64;
    const float* Q  = g_qq  + (size_t)z * G * QK;
    const float* Km = g_qkh + (size_t)z * G * QK;
    __shared__ float Qs[16][64];
    __shared__ float Ks[16][64];
    __shared__ float rt[32];
    int tid = threadIdx.x, tx = tid & 15, ty = tid >> 4;
    if (tid < 32) rt[tid] = rel_table[tid] * 11.313708498984761f;
    float acc[4][4] = {};
    for (int d0 = 0; d0 < QK; d0 += 16) {
        int row = tid >> 2, dc = (tid & 3) * 4;
        float4 q  = *(const float4*)&Q [(m0 + row) * QK + d0 + dc];
        float4 k4 = *(const float4*)&Km[(n0 + row) * QK + d0 + dc];
        Qs[dc + 0][row] = q.x;  Qs[dc + 1][row] = q.y;
        Qs[dc + 2][row] = q.z;  Qs[dc + 3][row] = q.w;
        Ks[dc + 0][row] = k4.x; Ks[dc + 1][row] = k4.y;
        Ks[dc + 2][row] = k4.z; Ks[dc + 3][row] = k4.w;
        __syncthreads();
#pragma unroll
        for (int kk = 0; kk < 16; kk++) {
            float ra[4], rb[4];
            *(float4*)ra = *(float4*)&Qs[kk][ty * 4];
            *(float4*)rb = *(float4*)&Ks[kk][tx * 4];
#pragma unroll
            for (int i = 0; i < 4; i++)
#pragma unroll
                for (int j = 0; j < 4; j++)
                    acc[i][j] += ra[i] * rb[j];
        }
        __syncthreads();
    }
    const float inv_lr = 0.48089834696298783f;
#pragma unroll
    for (int i = 0; i < 4; i++) {
        int gi = m0 + ty * 4 + i;
#pragma unroll
        for (int j = 0; j < 4; j++) {
            int gj = n0 + tx * 4 + j;
            float sim = acc[i][j] * (1.0f / G);
            int n = gi - gj;
            int bucket;
            if (n <= 0)      bucket = 0;
            else if (n < 16) bucket = n;
            else {
                bucket = 16 + (int)(logf((float)n * (1.0f / 16.0f)) * inv_lr * 16.0f);
                if (bucket > 31) bucket = 31;
            }
            sim += rt[bucket];
            float a = sim > 0.f ? sim * sim : 0.f;
            if (gj > gi) a = 0.f;
            g_attn[(size_t)z * (G * G) + gi * G + gj] = rtf(a);
        }
    }
}

// ---------------- exclusive group cumsum of lin_kv (tf32-rounded output) ----------------
__global__ void cumsum_kernel() {
    int p = blockIdx.x * blockDim.x + threadIdx.x;
    if (p >= NB * QK * HID) return;
    int b = p / (QK * HID);
    int off = p - b * (QK * HID);
    float acc = 0.f;
#pragma unroll
    for (int g = 0; g < NGPB; g++) {
        size_t idx = (size_t)(b * NGPB + g) * (QK * HID) + off;
        float t = g_linkv[idx];
        g_linkv[idx] = rtf(acc);
        acc += t;
    }
}

// ---------------- tf32 mma.sync GEMM, 128x128 CTA tile, K-chunk 32 ----------------
// D[m][n] = sum_k A[m][k]*B[n][k], both operands K-major (row.col for mma.sync)
// CFG 1: A=g_normed, B=g_WhT (x<32) / g_WqkT (x==32), M=16384, K=1024
//        epilogue: n0<2048 -> silu->g_vT (transposed); n0<4096 -> silu->g_gate;
//                  n0>=4096 -> qk heads: qq/lq/qkh row-major + lkT transposed
// CFG 3: A=g_attn[z], B=g_vT[z],   M=256, N=2048,K=256; -> g_ao
// CFG 4: A=g_vT[z],  B=g_lkT[z],   M=2048,N=128, K=256; *(1/256) -> g_linkv [e][d]
// CFG 5: A=g_lq[z],  B=g_linkv[z], M=256, N=2048,K=128; g_ao=rtf((g_ao+v)*g_gate)
// CFG 6: A=g_ao,     B=g_WoutT,  M=16384,N=1024,K=2048; +bout+x -> out
#define STG     18432                       // one 128x32 operand stage (stride 36 floats)
#define GEMM_SMEM (4 * STG)                 // 73728: As0,Bs0,As1,Bs1 (epilogue reuses)

__device__ __forceinline__ uint32_t smem_u32(const void* p) {
    uint32_t a;
    asm("{ .reg .u64 t; cvta.to.shared.u64 t, %1; cvt.u32.u64 %0, t; }" : "=r"(a) : "l"(p));
    return a;
}
__device__ __forceinline__ void mma8(float* d, const uint32_t* a, const uint32_t* b) {
    asm volatile(
        "mma.sync.aligned.m16n8k8.row.col.f32.tf32.tf32.f32 "
        "{%0,%1,%2,%3}, {%4,%5,%6,%7}, {%8,%9}, {%0,%1,%2,%3};"
        : "+f"(d[0]), "+f"(d[1]), "+f"(d[2]), "+f"(d[3])
        : "r"(a[0]), "r"(a[1]), "r"(a[2]), "r"(a[3]), "r"(b[0]), "r"(b[1]));
}

template <int CFG>
__global__ void __launch_bounds__(256)
gemm_tc(const float* __restrict__ pbias, const float* __restrict__ paux,
        float* __restrict__ pout,
        const float* __restrict__ pbias2, const float* __restrict__ pqkw,
        const float* __restrict__ pqkb) {
    constexpr int K  = (CFG == 1) ? 1024
                     : (CFG == 3 || CFG == 4) ? 256
                     : (CFG == 5) ? 128 : 2048;
    constexpr int NC = K / 32;

    extern __shared__ char smem[];
    uint32_t sbase = smem_u32(smem);
    float* smf = (float*)smem;

    int tid = threadIdx.x, w = tid >> 5, lane = tid & 31;
    int grpL = lane >> 2, tig = lane & 3;
    int wm = w >> 2, wn = w & 3;            // 2 x 4 warp grid
    int z = blockIdx.z;
    int n0 = blockIdx.x * 128, m0 = blockIdx.y * 128;

    const float* A; const float* B;
    if      (CFG == 1) { A = g_normed;                     B = g_WhT;  }
    else if (CFG == 3) { A = g_attn + (size_t)z * G * G;   B = g_vT + (size_t)z * HID * G; }
    else if (CFG == 4) { A = g_vT + (size_t)z * HID * G;   B = g_lkT + (size_t)z * QK * G; }
    else if (CFG == 5) { A = g_lq + (size_t)z * G * QK;    B = g_linkv + (size_t)z * HID * QK; }
    else               { A = g_ao;                         B = g_WoutT; }

    // operand tile base pointers (CFG1 x-block 32 reads WqkT)
    const float* Atile = A + (size_t)m0 * K;
    const float* Btile = (CFG == 1 && n0 >= HV2)
                       ? g_WqkT + (size_t)(n0 - HV2) * K
                       : B + (size_t)n0 * K;

    float acc[4][4][4];
#pragma unroll
    for (int i = 0; i < 4; i++)
#pragma unroll
        for (int j = 0; j < 4; j++)
#pragma unroll
            for (int r = 0; r < 4; r++) acc[i][j][r] = 0.f;

    int ldr = tid >> 3, ldc = (tid & 7) * 4;          // global->smem mapping

    // prime stage 0
    {
#pragma unroll
        for (int j = 0; j < 4; ++j) {
            int r = ldr + j * 32;
            uint32_t da = sbase + (uint32_t)((r * 36 + ldc) * 4);
            uint32_t db = da + STG;
            asm volatile("cp.async.cg.shared.global [%0], [%1], 16;"
                         :: "r"(da), "l"(Atile + (size_t)r * K + ldc));
            asm volatile("cp.async.cg.shared.global [%0], [%1], 16;"
                         :: "r"(db), "l"(Btile + (size_t)r * K + ldc));
        }
        asm volatile("cp.async.commit_group;");
    }

    for (int c = 0; c < NC; ++c) {
        if (c + 1 < NC) {
            int st = (c + 1) & 1;
            const float* Ap = Atile + (c + 1) * 32;
            const float* Bp = Btile + (c + 1) * 32;
#pragma unroll
            for (int j = 0; j < 4; ++j) {
                int r = ldr + j * 32;
                uint32_t da = sbase + (uint32_t)(st * 2 * STG + (r * 36 + ldc) * 4);
                uint32_t db = da + STG;
                asm volatile("cp.async.cg.shared.global [%0], [%1], 16;"
                             :: "r"(da), "l"(Ap + (size_t)r * K + ldc));
                asm volatile("cp.async.cg.shared.global [%0], [%1], 16;"
                             :: "r"(db), "l"(Bp + (size_t)r * K + ldc));
            }
            asm volatile("cp.async.commit_group;");
            asm volatile("cp.async.wait_group 1;");
        } else {
            asm volatile("cp.async.wait_group 0;");
        }
        __syncthreads();

        const uint32_t* As = (const uint32_t*)(smem + (c & 1) * 2 * STG);
        const uint32_t* Bs = As + STG / 4;
#pragma unroll
        for (int k8 = 0; k8 < 4; ++k8) {
            int k0 = k8 * 8;
            uint32_t af[4][4], bf[4][2];
#pragma unroll
            for (int i = 0; i < 4; ++i) {
                int rb = wm * 64 + i * 16 + grpL;
                af[i][0] = As[rb * 36 + k0 + tig];
                af[i][1] = As[(rb + 8) * 36 + k0 + tig];
                af[i][2] = As[rb * 36 + k0 + tig + 4];
                af[i][3] = As[(rb + 8) * 36 + k0 + tig + 4];
            }
#pragma unroll
            for (int j = 0; j < 4; ++j) {
                int nb = wn * 32 + j * 8 + grpL;
                bf[j][0] = Bs[nb * 36 + k0 + tig];
                bf[j][1] = Bs[nb * 36 + k0 + tig + 4];
            }
#pragma unroll
            for (int i = 0; i < 4; ++i)
#pragma unroll
                for (int j = 0; j < 4; ++j)
                    mma8(acc[i][j], af[i], bf[j]);
        }
        __syncthreads();
    }

    // ---- stage accumulators into smem [128][132] ----
#pragma unroll
    for (int i = 0; i < 4; ++i) {
#pragma unroll
        for (int j = 0; j < 4; ++j) {
            int row = wm * 64 + i * 16 + grpL;
            int col = wn * 32 + j * 8 + tig * 2;
            smf[row * 132 + col]           = acc[i][j][0];
            smf[row * 132 + col + 1]       = acc[i][j][1];
            smf[(row + 8) * 132 + col]     = acc[i][j][2];
            smf[(row + 8) * 132 + col + 1] = acc[i][j][3];
        }
    }
    __syncthreads();

    // ---- epilogue / global write ----
    if (CFG == 1 && n0 < HID) {
        // v branch: write transposed into g_vT[grp][gn][t] (tf32-rounded: GEMM operand)
        int grp = m0 >> 8, tg0 = m0 & 255;
#pragma unroll
        for (int it = 0; it < 16; ++it) {
            int cc = it * 8 + w;               // 0..127
            int gn = n0 + cc;
            float bias = pbias[gn];
            int t = lane * 4;
            float4 o;
            o.x = rtf(silu(smf[(t + 0) * 132 + cc] + bias));
            o.y = rtf(silu(smf[(t + 1) * 132 + cc] + bias));
            o.z = rtf(silu(smf[(t + 2) * 132 + cc] + bias));
            o.w = rtf(silu(smf[(t + 3) * 132 + cc] + bias));
            *(float4*)&g_vT[((size_t)grp * HID + gn) * G + tg0 + t] = o;
        }
        return;
    }
    if (CFG == 1 && n0 >= HV2) {
        // qk heads branch: s = silu(acc + bqk); emit qq/lq/qkh row-major, lkT transposed
        int grp = m0 >> 8, tg0 = m0 & 255;
        // pass 1: compute s in-place in smf, write qq/lq/qkh
#pragma unroll
        for (int it = 0; it < 16; ++it) {
            int idx = tid + it * 256;          // 128 rows x 32 float4
            int r = idx >> 5, c4 = (idx & 31) * 4;
            int tok = m0 + r;
            float4 bq = *(const float4*)&pbias2[c4];
            float4 s;
            s.x = silu(smf[r * 132 + c4 + 0] + bq.x);
            s.y = silu(smf[r * 132 + c4 + 1] + bq.y);
            s.z = silu(smf[r * 132 + c4 + 2] + bq.z);
            s.w = silu(smf[r * 132 + c4 + 3] + bq.w);
            smf[r * 132 + c4 + 0] = s.x; smf[r * 132 + c4 + 1] = s.y;
            smf[r * 132 + c4 + 2] = s.z; smf[r * 132 + c4 + 3] = s.w;
            float4 w0 = *(const float4*)&pqkw[c4];
            float4 b0 = *(const float4*)&pqkb[c4];
            float4 o0;
            o0.x = s.x * w0.x + b0.x; o0.y = s.y * w0.y + b0.y;
            o0.z = s.z * w0.z + b0.z; o0.w = s.w * w0.w + b0.w;
            *(float4*)&g_qq[(size_t)tok * QK + c4] = o0;
            float4 w1 = *(const float4*)&pqkw[QK + c4];
            float4 b1 = *(const float4*)&pqkb[QK + c4];
            float4 o1;
            o1.x = rtf(s.x * w1.x + b1.x); o1.y = rtf(s.y * w1.y + b1.y);
            o1.z = rtf(s.z * w1.z + b1.z); o1.w = rtf(s.w * w1.w + b1.w);
            *(float4*)&g_lq[(size_t)tok * QK + c4] = o1;
            float4 w2 = *(const float4*)&pqkw[2 * QK + c4];
            float4 b2 = *(const float4*)&pqkb[2 * QK + c4];
            float4 o2;
            o2.x = s.x * w2.x + b2.x; o2.y = s.y * w2.y + b2.y;
            o2.z = s.z * w2.z + b2.z; o2.w = s.w * w2.w + b2.w;
            *(float4*)&g_qkh[(size_t)tok * QK + c4] = o2;
        }
        __syncthreads();
        // pass 2: transposed lin_k write
#pragma unroll
        for (int it = 0; it < 16; ++it) {
            int cc = it * 8 + w;               // d = 0..127
            float w3 = pqkw[3 * QK + cc], b3 = pqkb[3 * QK + cc];
            int t = lane * 4;
            float4 o;
            o.x = rtf(smf[(t + 0) * 132 + cc] * w3 + b3);
            o.y = rtf(smf[(t + 1) * 132 + cc] * w3 + b3);
            o.z = rtf(smf[(t + 2) * 132 + cc] * w3 + b3);
            o.w = rtf(smf[(t + 3) * 132 + cc] * w3 + b3);
            *(float4*)&g_lkT[((size_t)grp * QK + cc) * G + tg0 + t] = o;
        }
        return;
    }
#pragma unroll
    for (int it = 0; it < 16; ++it) {
        int idx = tid + it * 256;              // 4096 float4 slots
        int r = idx >> 5, c4 = (idx & 31) * 4;
        int gm = m0 + r, gn = n0 + c4;
        float v0 = smf[r * 132 + c4 + 0];
        float v1 = smf[r * 132 + c4 + 1];
        float v2 = smf[r * 132 + c4 + 2];
        float v3 = smf[r * 132 + c4 + 3];
        if (CFG == 1) {                        // gate branch (2048 <= n0 < 4096)
            float4 o;
            o.x = silu(v0 + pbias[gn + 0]); o.y = silu(v1 + pbias[gn + 1]);
            o.z = silu(v2 + pbias[gn + 2]); o.w = silu(v3 + pbias[gn + 3]);
            *(float4*)&g_gate[(size_t)gm * HID + (gn - HID)] = o;
        } else if (CFG == 3) {                 // fp32 consumer (CFG5 epilogue)
            float4 o = make_float4(v0, v1, v2, v3);
            *(float4*)&g_ao[((size_t)z * G + gm) * HID + gn] = o;
        } else if (CFG == 4) {                 // cumsum rounds later
            float4 o = make_float4(v0 * (1.0f / G), v1 * (1.0f / G),
                                   v2 * (1.0f / G), v3 * (1.0f / G));
            *(float4*)&g_linkv[((size_t)z * HID + gm) * QK + gn] = o;
        } else if (CFG == 5) {                 // tf32-rounded: feeds CFG6 A
            size_t i0 = ((size_t)z * G + gm) * HID + gn;
            float4 q = *(const float4*)&g_ao[i0];
            float4 gt = *(const float4*)&g_gate[i0];
            float4 o;
            o.x = rtf((q.x + v0) * gt.x); o.y = rtf((q.y + v1) * gt.y);
            o.z = rtf((q.z + v2) * gt.z); o.w = rtf((q.w + v3) * gt.w);
            *(float4*)&g_ao[i0] = o;
        } else {                               // CFG 6
            size_t i0 = (size_t)gm * DIM + gn;
            float4 xr = *(const float4*)&paux[i0];
            float4 o;
            o.x = v0 + pbias[gn + 0] + xr.x; o.y = v1 + pbias[gn + 1] + xr.y;
            o.z = v2 + pbias[gn + 2] + xr.z; o.w = v3 + pbias[gn + 3] + xr.w;
            *(float4*)&pout[i0] = o;
        }
    }
}

// ---------------- launch ----------------
extern "C" void kernel_launch(void* const* d_in, const int* in_sizes, int n_in,
                              void* d_out, int out_size) {
    const float* x    = (const float*)d_in[0];
    const float* ln_w = (const float*)d_in[1];
    const float* ln_b = (const float*)d_in[2];
    const float* Wh   = (const float*)d_in[3];
    const float* bh   = (const float*)d_in[4];
    const float* Wqk  = (const float*)d_in[5];
    const float* bqk  = (const float*)d_in[6];
    const float* qk_w = (const float*)d_in[7];
    const float* qk_b = (const float*)d_in[8];
    const float* rel  = (const float*)d_in[9];
    const float* Wout = (const float*)d_in[10];
    const float* bout = (const float*)d_in[11];
    float* out = (float*)d_out;

    cudaFuncSetAttribute(gemm_tc<1>, cudaFuncAttributeMaxDynamicSharedMemorySize, GEMM_SMEM);
    cudaFuncSetAttribute(gemm_tc<3>, cudaFuncAttributeMaxDynamicSharedMemorySize, GEMM_SMEM);
    cudaFuncSetAttribute(gemm_tc<4>, cudaFuncAttributeMaxDynamicSharedMemorySize, GEMM_SMEM);
    cudaFuncSetAttribute(gemm_tc<5>, cudaFuncAttributeMaxDynamicSharedMemorySize, GEMM_SMEM);
    cudaFuncSetAttribute(gemm_tc<6>, cudaFuncAttributeMaxDynamicSharedMemorySize, GEMM_SMEM);

    float* WhT;   cudaGetSymbolAddress((void**)&WhT,   g_WhT);
    float* WqkT;  cudaGetSymbolAddress((void**)&WqkT,  g_WqkT);
    float* WoutT; cudaGetSymbolAddress((void**)&WoutT, g_WoutT);

    // weight transposes (K-major B operands, tf32-rounded)
    transpose_k<<<dim3(HV2 / 32, DIM / 32), dim3(32, 8)>>>(Wh,   WhT,   DIM, HV2);
    transpose_k<<<dim3(QK  / 32, DIM / 32), dim3(32, 8)>>>(Wqk,  WqkT,  DIM, QK);
    transpose_k<<<dim3(DIM / 32, HID / 32), dim3(32, 8)>>>(Wout, WoutT, HID, DIM);

    // 1) LayerNorm
    ln_kernel<<<NTOK, 256>>>(x, ln_w, ln_b);

    // 2) fused: hv = silu(normed @ [Wh|Wqk] + [bh|bqk]) -> vT + gate + qk heads
    gemm_tc<1><<<dim3(HV2 / 128 + 1, NTOK / 128, 1), 256, GEMM_SMEM>>>(
        bh, nullptr, nullptr, bqk, qk_w, qk_b);

    // 3) attn scores
    attn_kernel<<<dim3(4, 4, NGRP), 256>>>(rel);

    // 4) quad_out = attn @ v
    gemm_tc<3><<<dim3(HID / 128, G / 128, NGRP), 256, GEMM_SMEM>>>(
        nullptr, nullptr, nullptr, nullptr, nullptr, nullptr);

    // 5) lin_kv = v^T @ lin_k / g   -> [e][d]
    gemm_tc<4><<<dim3(1, HID / 128, NGRP), 256, GEMM_SMEM>>>(
        nullptr, nullptr, nullptr, nullptr, nullptr, nullptr);

    // 6) exclusive group cumsum
    cumsum_kernel<<<(NB * QK * HID) / 256, 256>>>();

    // 7) lin_out = lin_q @ lin_kv ; ao = gate*(quad+lin)
    gemm_tc<5><<<dim3(HID / 128, G / 128, NGRP), 256, GEMM_SMEM>>>(
        nullptr, nullptr, nullptr, nullptr, nullptr, nullptr);

    // 8) out = ao @ Wout + bout + x
    gemm_tc<6><<<dim3(DIM / 128, NTOK / 128, 1), 256, GEMM_SMEM>>>(
        bout, x, out, nullptr, nullptr, nullptr);
}

// round 9
// speedup vs baseline: 1.7268x; 1.6446x over previous
#include <cuda_runtime.h>
#include <math.h>
#include <stdint.h>

// ---------------- problem constants ----------------
#define NTOK   16384        // 4 * 4096
#define DIM    1024
#define HID    2048
#define HV2    4096         // 2*HID
#define QK     128
#define G      256
#define NGRP   64           // 4 batches * 16 groups
#define NB     4
#define NGPB   16
#define LN_EPS 1e-5f

// ---------------- scratch (device globals) ----------------
__device__ float g_normed[(size_t)NTOK * DIM];
__device__ float g_vT    [(size_t)NGRP * HID * G];   // v transposed per group: [g][e][t]
__device__ float g_gate  [(size_t)NTOK * HID];
__device__ float g_qq    [(size_t)NTOK * QK];        // [g][t][d]
__device__ float g_lq    [(size_t)NTOK * QK];
__device__ float g_qkh   [(size_t)NTOK * QK];
__device__ float g_lkT   [(size_t)NGRP * QK * G];    // lin_k transposed: [g][d][t]
__device__ float g_attn  [(size_t)NGRP * G * G];
__device__ float g_ao    [(size_t)NTOK * HID];
__device__ float g_linkv [(size_t)NGRP * HID * QK];  // [g][e][d]
__device__ float g_WhT   [(size_t)HV2 * DIM];
__device__ float g_WqkT  [(size_t)QK * DIM];
__device__ float g_WoutT [(size_t)DIM * HID];

__device__ __forceinline__ float silu(float x) { return x / (1.0f + expf(-x)); }
// round-to-nearest tf32 (removes HMMA truncation bias)
__device__ __forceinline__ float rtf(float f) {
    uint32_t u;
    asm("cvt.rna.tf32.f32 %0, %1;" : "=r"(u) : "f"(f));
    return __uint_as_float(u);
}

// ---------------- LayerNorm (UNCHANGED: clock canary) ----------------
__global__ void ln_kernel(const float* __restrict__ x,
                          const float* __restrict__ w,
                          const float* __restrict__ b) {
    int row = blockIdx.x;
    const float* xr = x + (size_t)row * DIM;
    float s = 0.f, s2 = 0.f;
    for (int i = threadIdx.x; i < DIM; i += blockDim.x) {
        float v = xr[i]; s += v; s2 += v * v;
    }
    __shared__ float sh[8], sh2[8];
    for (int o = 16; o > 0; o >>= 1) {
        s  += __shfl_down_sync(0xffffffffu, s, o);
        s2 += __shfl_down_sync(0xffffffffu, s2, o);
    }
    int wid = threadIdx.x >> 5, lane = threadIdx.x & 31;
    if (lane == 0) { sh[wid] = s; sh2[wid] = s2; }
    __syncthreads();
    if (threadIdx.x == 0) {
        float a = 0.f, a2 = 0.f;
        for (int i = 0; i < (int)(blockDim.x >> 5); i++) { a += sh[i]; a2 += sh2[i]; }
        sh[0] = a; sh2[0] = a2;
    }
    __syncthreads();
    float mu  = sh[0] * (1.0f / DIM);
    float var = sh2[0] * (1.0f / DIM) - mu * mu;
    float inv = rsqrtf(var + LN_EPS);
    float* o = g_normed + (size_t)row * DIM;
    for (int i = threadIdx.x; i < DIM; i += blockDim.x)
        o[i] = rtf((xr[i] - mu) * inv * w[i] + b[i]);
}

// ---------------- tiled transpose + tf32 rounding: in[R][C] -> out[C][R] ----------------
__global__ void transpose_k(const float* __restrict__ in, float* __restrict__ out,
                            int R, int C) {
    __shared__ float t[32][33];
    int c0 = blockIdx.x * 32, r0 = blockIdx.y * 32;
    int x = threadIdx.x, y = threadIdx.y;
#pragma unroll
    for (int j = 0; j < 32; j += 8)
        t[y + j][x] = in[(size_t)(r0 + y + j) * C + c0 + x];
    __syncthreads();
#pragma unroll
    for (int j = 0; j < 32; j += 8)
        out[(size_t)(c0 + y + j) * R + r0 + x] = rtf(t[x][y + j]);
}

// ---------------- sim / bias / relu^2 / mask (fp32 math, tf32-rounded output) ----------------
__global__ void __launch_bounds__(256) attn_kernel(const float* __restrict__ rel_table) {
    int z  = blockIdx.z;
    int m0 = blockIdx.y * 64, n0 = blockIdx.x * 64;
    const float* Q  = g_qq  + (size_t)z * G * QK;
    const float* Km = g_qkh + (size_t)z * G * QK;
    __shared__ float Qs[16][64];
    __shared__ float Ks[16][64];
    __shared__ float rt[32];
    int tid = threadIdx.x, tx = tid & 15, ty = tid >> 4;
    if (tid < 32) rt[tid] = rel_table[tid] * 11.313708498984761f;
    float acc[4][4] = {};
    for (int d0 = 0; d0 < QK; d0 += 16) {
        int row = tid >> 2, dc = (tid & 3) * 4;
        float4 q  = *(const float4*)&Q [(m0 + row) * QK + d0 + dc];
        float4 k4 = *(const float4*)&Km[(n0 + row) * QK + d0 + dc];
        Qs[dc + 0][row] = q.x;  Qs[dc + 1][row] = q.y;
        Qs[dc + 2][row] = q.z;  Qs[dc + 3][row] = q.w;
        Ks[dc + 0][row] = k4.x; Ks[dc + 1][row] = k4.y;
        Ks[dc + 2][row] = k4.z; Ks[dc + 3][row] = k4.w;
        __syncthreads();
#pragma unroll
        for (int kk = 0; kk < 16; kk++) {
            float ra[4], rb[4];
            *(float4*)ra = *(float4*)&Qs[kk][ty * 4];
            *(float4*)rb = *(float4*)&Ks[kk][tx * 4];
#pragma unroll
            for (int i = 0; i < 4; i++)
#pragma unroll
                for (int j = 0; j < 4; j++)
                    acc[i][j] += ra[i] * rb[j];
        }
        __syncthreads();
    }
    const float inv_lr = 0.48089834696298783f;
#pragma unroll
    for (int i = 0; i < 4; i++) {
        int gi = m0 + ty * 4 + i;
#pragma unroll
        for (int j = 0; j < 4; j++) {
            int gj = n0 + tx * 4 + j;
            float sim = acc[i][j] * (1.0f / G);
            int n = gi - gj;
            int bucket;
            if (n <= 0)      bucket = 0;
            else if (n < 16) bucket = n;
            else {
                bucket = 16 + (int)(logf((float)n * (1.0f / 16.0f)) * inv_lr * 16.0f);
                if (bucket > 31) bucket = 31;
            }
            sim += rt[bucket];
            float a = sim > 0.f ? sim * sim : 0.f;
            if (gj > gi) a = 0.f;
            g_attn[(size_t)z * (G * G) + gi * G + gj] = rtf(a);
        }
    }
}

// ---------------- exclusive group cumsum of lin_kv (tf32-rounded output) ----------------
__global__ void cumsum_kernel() {
    int p = blockIdx.x * blockDim.x + threadIdx.x;
    if (p >= NB * QK * HID) return;
    int b = p / (QK * HID);
    int off = p - b * (QK * HID);
    float acc = 0.f;
#pragma unroll
    for (int g = 0; g < NGPB; g++) {
        size_t idx = (size_t)(b * NGPB + g) * (QK * HID) + off;
        float t = g_linkv[idx];
        g_linkv[idx] = rtf(acc);
        acc += t;
    }
}

// ---------------- tf32 mma.sync GEMM, 128x128 CTA tile, K-chunk 32, LDSM fragments ----------------
// D[m][n] = sum_k A[m][k]*B[n][k], both operands K-major (row.col for mma.sync)
// CFG 1: A=g_normed, B=g_WhT (x<32) / g_WqkT (x==32), M=16384, K=1024
//        epilogue: n0<2048 -> silu->g_vT (transposed); n0<4096 -> silu->g_gate;
//                  n0>=4096 -> qk heads: qq/lq/qkh row-major + lkT transposed
// CFG 3: A=g_attn[z], B=g_vT[z],   M=256, N=2048,K=256; -> g_ao
// CFG 4: A=g_vT[z],  B=g_lkT[z],   M=2048,N=128, K=256; *(1/256) -> g_linkv [e][d]
// CFG 5: A=g_lq[z],  B=g_linkv[z], M=256, N=2048,K=128; g_ao=rtf((g_ao+v)*g_gate)
// CFG 6: A=g_ao,     B=g_WoutT,  M=16384,N=1024,K=2048; +bout+x -> out
#define STG     18432                       // one 128x32 operand stage (stride 36 floats)
#define GEMM_SMEM (4 * STG)                 // 73728: As0,Bs0,As1,Bs1 (epilogue reuses)

__device__ __forceinline__ uint32_t smem_u32(const void* p) {
    uint32_t a;
    asm("{ .reg .u64 t; cvta.to.shared.u64 t, %1; cvt.u32.u64 %0, t; }" : "=r"(a) : "l"(p));
    return a;
}
__device__ __forceinline__ void mma8(float* d, const uint32_t* a, const uint32_t* b) {
    asm volatile(
        "mma.sync.aligned.m16n8k8.row.col.f32.tf32.tf32.f32 "
        "{%0,%1,%2,%3}, {%4,%5,%6,%7}, {%8,%9}, {%0,%1,%2,%3};"
        : "+f"(d[0]), "+f"(d[1]), "+f"(d[2]), "+f"(d[3])
        : "r"(a[0]), "r"(a[1]), "r"(a[2]), "r"(a[3]), "r"(b[0]), "r"(b[1]));
}
__device__ __forceinline__ void ldsm4(uint32_t& r0, uint32_t& r1, uint32_t& r2, uint32_t& r3,
                                      uint32_t addr) {
    asm volatile("ldmatrix.sync.aligned.m8n8.x4.shared.b16 {%0,%1,%2,%3}, [%4];"
                 : "=r"(r0), "=r"(r1), "=r"(r2), "=r"(r3) : "r"(addr));
}

template <int CFG>
__global__ void __launch_bounds__(256)
gemm_tc(const float* __restrict__ pbias, const float* __restrict__ paux,
        float* __restrict__ pout,
        const float* __restrict__ pbias2, const float* __restrict__ pqkw,
        const float* __restrict__ pqkb) {
    constexpr int K  = (CFG == 1) ? 1024
                     : (CFG == 3 || CFG == 4) ? 256
                     : (CFG == 5) ? 128 : 2048;
    constexpr int NC = K / 32;

    extern __shared__ char smem[];
    uint32_t sbase = smem_u32(smem);
    float* smf = (float*)smem;

    int tid = threadIdx.x, w = tid >> 5, lane = tid & 31;
    int grpL = lane >> 2, tig = lane & 3;
    int wm = w >> 2, wn = w & 3;            // 2 x 4 warp grid
    int z = blockIdx.z;
    int n0 = blockIdx.x * 128, m0 = blockIdx.y * 128;

    const float* A; const float* B;
    if      (CFG == 1) { A = g_normed;                     B = g_WhT;  }
    else if (CFG == 3) { A = g_attn + (size_t)z * G * G;   B = g_vT + (size_t)z * HID * G; }
    else if (CFG == 4) { A = g_vT + (size_t)z * HID * G;   B = g_lkT + (size_t)z * QK * G; }
    else if (CFG == 5) { A = g_lq + (size_t)z * G * QK;    B = g_linkv + (size_t)z * HID * QK; }
    else               { A = g_ao;                         B = g_WoutT; }

    // operand tile base pointers (CFG1 x-block 32 reads WqkT)
    const float* Atile = A + (size_t)m0 * K;
    const float* Btile = (CFG == 1 && n0 >= HV2)
                       ? g_WqkT + (size_t)(n0 - HV2) * K
                       : B + (size_t)n0 * K;

    float acc[4][4][4];
#pragma unroll
    for (int i = 0; i < 4; i++)
#pragma unroll
        for (int j = 0; j < 4; j++)
#pragma unroll
            for (int r = 0; r < 4; r++) acc[i][j][r] = 0.f;

    int ldr = tid >> 3, ldc = (tid & 7) * 4;          // global->smem mapping

    // ldmatrix lane-relative byte offsets (q = matrix id, rL = row within matrix)
    int q = lane >> 3, rL = lane & 7;
    uint32_t laneA = (uint32_t)(((wm * 64 + (q & 1) * 8 + rL) * 36 + (q >> 1) * 4) * 4);
    uint32_t laneB = (uint32_t)(((wn * 32 + (q >> 1) * 8 + rL) * 36 + (q & 1) * 4) * 4) + STG;

    // prime stage 0
    {
#pragma unroll
        for (int j = 0; j < 4; ++j) {
            int r = ldr + j * 32;
            uint32_t da = sbase + (uint32_t)((r * 36 + ldc) * 4);
            uint32_t db = da + STG;
            asm volatile("cp.async.cg.shared.global [%0], [%1], 16;"
                         :: "r"(da), "l"(Atile + (size_t)r * K + ldc));
            asm volatile("cp.async.cg.shared.global [%0], [%1], 16;"
                         :: "r"(db), "l"(Btile + (size_t)r * K + ldc));
        }
        asm volatile("cp.async.commit_group;");
    }

    for (int c = 0; c < NC; ++c) {
        if (c + 1 < NC) {
            int st = (c + 1) & 1;
            const float* Ap = Atile + (c + 1) * 32;
            const float* Bp = Btile + (c + 1) * 32;
#pragma unroll
            for (int j = 0; j < 4; ++j) {
                int r = ldr + j * 32;
                uint32_t da = sbase + (uint32_t)(st * 2 * STG + (r * 36 + ldc) * 4);
                uint32_t db = da + STG;
                asm volatile("cp.async.cg.shared.global [%0], [%1], 16;"
                             :: "r"(da), "l"(Ap + (size_t)r * K + ldc));
                asm volatile("cp.async.cg.shared.global [%0], [%1], 16;"
                             :: "r"(db), "l"(Bp + (size_t)r * K + ldc));
            }
            asm volatile("cp.async.commit_group;");
            asm volatile("cp.async.wait_group 1;");
        } else {
            asm volatile("cp.async.wait_group 0;");
        }
        __syncthreads();

        uint32_t abase = sbase + (uint32_t)((c & 1) * 2 * STG) + laneA;
        uint32_t bbase = sbase + (uint32_t)((c & 1) * 2 * STG) + laneB;
#pragma unroll
        for (int k8 = 0; k8 < 4; ++k8) {
            uint32_t af[4][4], bf[4][2];
#pragma unroll
            for (int i = 0; i < 4; ++i)
                ldsm4(af[i][0], af[i][1], af[i][2], af[i][3],
                      abase + (uint32_t)(i * 2304 + k8 * 32));
            ldsm4(bf[0][0], bf[0][1], bf[1][0], bf[1][1], bbase + (uint32_t)(k8 * 32));
            ldsm4(bf[2][0], bf[2][1], bf[3][0], bf[3][1],
                  bbase + (uint32_t)(2304 + k8 * 32));
#pragma unroll
            for (int i = 0; i < 4; ++i)
#pragma unroll
                for (int j = 0; j < 4; ++j)
                    mma8(acc[i][j], af[i], bf[j]);
        }
        __syncthreads();
    }

    // ---- stage accumulators into smem [128][132] ----
#pragma unroll
    for (int i = 0; i < 4; ++i) {
#pragma unroll
        for (int j = 0; j < 4; ++j) {
            int row = wm * 64 + i * 16 + grpL;
            int col = wn * 32 + j * 8 + tig * 2;
            smf[row * 132 + col]           = acc[i][j][0];
            smf[row * 132 + col + 1]       = acc[i][j][1];
            smf[(row + 8) * 132 + col]     = acc[i][j][2];
            smf[(row + 8) * 132 + col + 1] = acc[i][j][3];
        }
    }
    __syncthreads();

    // ---- epilogue / global write ----
    if (CFG == 1 && n0 < HID) {
        // v branch: write transposed into g_vT[grp][gn][t] (tf32-rounded: GEMM operand)
        int grp = m0 >> 8, tg0 = m0 & 255;
#pragma unroll
        for (int it = 0; it < 16; ++it) {
            int cc = it * 8 + w;               // 0..127
            int gn = n0 + cc;
            float bias = pbias[gn];
            int t = lane * 4;
            float4 o;
            o.x = rtf(silu(smf[(t + 0) * 132 + cc] + bias));
            o.y = rtf(silu(smf[(t + 1) * 132 + cc] + bias));
            o.z = rtf(silu(smf[(t + 2) * 132 + cc] + bias));
            o.w = rtf(silu(smf[(t + 3) * 132 + cc] + bias));
            *(float4*)&g_vT[((size_t)grp * HID + gn) * G + tg0 + t] = o;
        }
        return;
    }
    if (CFG == 1 && n0 >= HV2) {
        // qk heads branch: s = silu(acc + bqk); emit qq/lq/qkh row-major, lkT transposed
        int grp = m0 >> 8, tg0 = m0 & 255;
#pragma unroll
        for (int it = 0; it < 16; ++it) {
            int idx = tid + it * 256;          // 128 rows x 32 float4
            int r = idx >> 5, c4 = (idx & 31) * 4;
            int tok = m0 + r;
            float4 bq = *(const float4*)&pbias2[c4];
            float4 s;
            s.x = silu(smf[r * 132 + c4 + 0] + bq.x);
            s.y = silu(smf[r * 132 + c4 + 1] + bq.y);
            s.z = silu(smf[r * 132 + c4 + 2] + bq.z);
            s.w = silu(smf[r * 132 + c4 + 3] + bq.w);
            smf[r * 132 + c4 + 0] = s.x; smf[r * 132 + c4 + 1] = s.y;
            smf[r * 132 + c4 + 2] = s.z; smf[r * 132 + c4 + 3] = s.w;
            float4 w0 = *(const float4*)&pqkw[c4];
            float4 b0 = *(const float4*)&pqkb[c4];
            float4 o0;
            o0.x = s.x * w0.x + b0.x; o0.y = s.y * w0.y + b0.y;
            o0.z = s.z * w0.z + b0.z; o0.w = s.w * w0.w + b0.w;
            *(float4*)&g_qq[(size_t)tok * QK + c4] = o0;
            float4 w1 = *(const float4*)&pqkw[QK + c4];
            float4 b1 = *(const float4*)&pqkb[QK + c4];
            float4 o1;
            o1.x = rtf(s.x * w1.x + b1.x); o1.y = rtf(s.y * w1.y + b1.y);
            o1.z = rtf(s.z * w1.z + b1.z); o1.w = rtf(s.w * w1.w + b1.w);
            *(float4*)&g_lq[(size_t)tok * QK + c4] = o1;
            float4 w2 = *(const float4*)&pqkw[2 * QK + c4];
            float4 b2 = *(const float4*)&pqkb[2 * QK + c4];
            float4 o2;
            o2.x = s.x * w2.x + b2.x; o2.y = s.y * w2.y + b2.y;
            o2.z = s.z * w2.z + b2.z; o2.w = s.w * w2.w + b2.w;
            *(float4*)&g_qkh[(size_t)tok * QK + c4] = o2;
        }
        __syncthreads();
        // pass 2: transposed lin_k write
#pragma unroll
        for (int it = 0; it < 16; ++it) {
            int cc = it * 8 + w;               // d = 0..127
            float w3 = pqkw[3 * QK + cc], b3 = pqkb[3 * QK + cc];
            int t = lane * 4;
            float4 o;
            o.x = rtf(smf[(t + 0) * 132 + cc] * w3 + b3);
            o.y = rtf(smf[(t + 1) * 132 + cc] * w3 + b3);
            o.z = rtf(smf[(t + 2) * 132 + cc] * w3 + b3);
            o.w = rtf(smf[(t + 3) * 132 + cc] * w3 + b3);
            *(float4*)&g_lkT[((size_t)grp * QK + cc) * G + tg0 + t] = o;
        }
        return;
    }
#pragma unroll
    for (int it = 0; it < 16; ++it) {
        int idx = tid + it * 256;              // 4096 float4 slots
        int r = idx >> 5, c4 = (idx & 31) * 4;
        int gm = m0 + r, gn = n0 + c4;
        float v0 = smf[r * 132 + c4 + 0];
        float v1 = smf[r * 132 + c4 + 1];
        float v2 = smf[r * 132 + c4 + 2];
        float v3 = smf[r * 132 + c4 + 3];
        if (CFG == 1) {                        // gate branch (2048 <= n0 < 4096)
            float4 o;
            o.x = silu(v0 + pbias[gn + 0]); o.y = silu(v1 + pbias[gn + 1]);
            o.z = silu(v2 + pbias[gn + 2]); o.w = silu(v3 + pbias[gn + 3]);
            *(float4*)&g_gate[(size_t)gm * HID + (gn - HID)] = o;
        } else if (CFG == 3) {                 // fp32 consumer (CFG5 epilogue)
            float4 o = make_float4(v0, v1, v2, v3);
            *(float4*)&g_ao[((size_t)z * G + gm) * HID + gn] = o;
        } else if (CFG == 4) {                 // cumsum rounds later
            float4 o = make_float4(v0 * (1.0f / G), v1 * (1.0f / G),
                                   v2 * (1.0f / G), v3 * (1.0f / G));
            *(float4*)&g_linkv[((size_t)z * HID + gm) * QK + gn] = o;
        } else if (CFG == 5) {                 // tf32-rounded: feeds CFG6 A
            size_t i0 = ((size_t)z * G + gm) * HID + gn;
            float4 qv = *(const float4*)&g_ao[i0];
            float4 gt = *(const float4*)&g_gate[i0];
            float4 o;
            o.x = rtf((qv.x + v0) * gt.x); o.y = rtf((qv.y + v1) * gt.y);
            o.z = rtf((qv.z + v2) * gt.z); o.w = rtf((qv.w + v3) * gt.w);
            *(float4*)&g_ao[i0] = o;
        } else {                               // CFG 6
            size_t i0 = (size_t)gm * DIM + gn;
            float4 xr = *(const float4*)&paux[i0];
            float4 o;
            o.x = v0 + pbias[gn + 0] + xr.x; o.y = v1 + pbias[gn + 1] + xr.y;
            o.z = v2 + pbias[gn + 2] + xr.z; o.w = v3 + pbias[gn + 3] + xr.w;
            *(float4*)&pout[i0] = o;
        }
    }
}

// ---------------- launch ----------------
extern "C" void kernel_launch(void* const* d_in, const int* in_sizes, int n_in,
                              void* d_out, int out_size) {
    const float* x    = (const float*)d_in[0];
    const float* ln_w = (const float*)d_in[1];
    const float* ln_b = (const float*)d_in[2];
    const float* Wh   = (const float*)d_in[3];
    const float* bh   = (const float*)d_in[4];
    const float* Wqk  = (const float*)d_in[5];
    const float* bqk  = (const float*)d_in[6];
    const float* qk_w = (const float*)d_in[7];
    const float* qk_b = (const float*)d_in[8];
    const float* rel  = (const float*)d_in[9];
    const float* Wout = (const float*)d_in[10];
    const float* bout = (const float*)d_in[11];
    float* out = (float*)d_out;

    cudaFuncSetAttribute(gemm_tc<1>, cudaFuncAttributeMaxDynamicSharedMemorySize, GEMM_SMEM);
    cudaFuncSetAttribute(gemm_tc<3>, cudaFuncAttributeMaxDynamicSharedMemorySize, GEMM_SMEM);
    cudaFuncSetAttribute(gemm_tc<4>, cudaFuncAttributeMaxDynamicSharedMemorySize, GEMM_SMEM);
    cudaFuncSetAttribute(gemm_tc<5>, cudaFuncAttributeMaxDynamicSharedMemorySize, GEMM_SMEM);
    cudaFuncSetAttribute(gemm_tc<6>, cudaFuncAttributeMaxDynamicSharedMemorySize, GEMM_SMEM);

    float* WhT;   cudaGetSymbolAddress((void**)&WhT,   g_WhT);
    float* WqkT;  cudaGetSymbolAddress((void**)&WqkT,  g_WqkT);
    float* WoutT; cudaGetSymbolAddress((void**)&WoutT, g_WoutT);

    // weight transposes (K-major B operands, tf32-rounded)
    transpose_k<<<dim3(HV2 / 32, DIM / 32), dim3(32, 8)>>>(Wh,   WhT,   DIM, HV2);
    transpose_k<<<dim3(QK  / 32, DIM / 32), dim3(32, 8)>>>(Wqk,  WqkT,  DIM, QK);
    transpose_k<<<dim3(DIM / 32, HID / 32), dim3(32, 8)>>>(Wout, WoutT, HID, DIM);

    // 1) LayerNorm
    ln_kernel<<<NTOK, 256>>>(x, ln_w, ln_b);

    // 2) fused: hv = silu(normed @ [Wh|Wqk] + [bh|bqk]) -> vT + gate + qk heads
    gemm_tc<1><<<dim3(HV2 / 128 + 1, NTOK / 128, 1), 256, GEMM_SMEM>>>(
        bh, nullptr, nullptr, bqk, qk_w, qk_b);

    // 3) attn scores
    attn_kernel<<<dim3(4, 4, NGRP), 256>>>(rel);

    // 4) quad_out = attn @ v
    gemm_tc<3><<<dim3(HID / 128, G / 128, NGRP), 256, GEMM_SMEM>>>(
        nullptr, nullptr, nullptr, nullptr, nullptr, nullptr);

    // 5) lin_kv = v^T @ lin_k / g   -> [e][d]
    gemm_tc<4><<<dim3(1, HID / 128, NGRP), 256, GEMM_SMEM>>>(
        nullptr, nullptr, nullptr, nullptr, nullptr, nullptr);

    // 6) exclusive group cumsum
    cumsum_kernel<<<(NB * QK * HID) / 256, 256>>>();

    // 7) lin_out = lin_q @ lin_kv ; ao = gate*(quad+lin)
    gemm_tc<5><<<dim3(HID / 128, G / 128, NGRP), 256, GEMM_SMEM>>>(
        nullptr, nullptr, nullptr, nullptr, nullptr, nullptr);

    // 8) out = ao @ Wout + bout + x
    gemm_tc<6><<<dim3(DIM / 128, NTOK / 128, 1), 256, GEMM_SMEM>>>(
        bout, x, out, nullptr, nullptr, nullptr);
}

// round 10
// speedup vs baseline: 1.8042x; 1.0448x over previous
#include <cuda_runtime.h>
#include <math.h>
#include <stdint.h>

// ---------------- problem constants ----------------
#define NTOK   16384        // 4 * 4096
#define DIM    1024
#define HID    2048
#define HV2    4096         // 2*HID
#define QK     128
#define G      256
#define NGRP   64           // 4 batches * 16 groups
#define NB     4
#define NGPB   16
#define LN_EPS 1e-5f

// ---------------- scratch (device globals) ----------------
__device__ float g_normed[(size_t)NTOK * DIM];
__device__ float g_vT    [(size_t)NGRP * HID * G];   // v transposed per group: [g][e][t]
__device__ float g_gate  [(size_t)NTOK * HID];
__device__ float g_qq    [(size_t)NTOK * QK];        // [g][t][d] (tf32)
__device__ float g_lq    [(size_t)NTOK * QK];
__device__ float g_qkh   [(size_t)NTOK * QK];        // (tf32)
__device__ float g_lkT   [(size_t)NGRP * QK * G];    // lin_k transposed: [g][d][t]
__device__ float g_attn  [(size_t)NGRP * G * G];
__device__ float g_ao    [(size_t)NTOK * HID];
__device__ float g_linkv [(size_t)NGRP * HID * QK];  // [g][e][d]
__device__ float g_WhT   [(size_t)HV2 * DIM];
__device__ float g_WqkT  [(size_t)QK * DIM];
__device__ float g_WoutT [(size_t)DIM * HID];

__device__ __forceinline__ float silu(float x) { return x / (1.0f + expf(-x)); }
// round-to-nearest tf32 (removes HMMA truncation bias)
__device__ __forceinline__ float rtf(float f) {
    uint32_t u;
    asm("cvt.rna.tf32.f32 %0, %1;" : "=r"(u) : "f"(f));
    return __uint_as_float(u);
}

// ---------------- LayerNorm (UNCHANGED: clock canary) ----------------
__global__ void ln_kernel(const float* __restrict__ x,
                          const float* __restrict__ w,
                          const float* __restrict__ b) {
    int row = blockIdx.x;
    const float* xr = x + (size_t)row * DIM;
    float s = 0.f, s2 = 0.f;
    for (int i = threadIdx.x; i < DIM; i += blockDim.x) {
        float v = xr[i]; s += v; s2 += v * v;
    }
    __shared__ float sh[8], sh2[8];
    for (int o = 16; o > 0; o >>= 1) {
        s  += __shfl_down_sync(0xffffffffu, s, o);
        s2 += __shfl_down_sync(0xffffffffu, s2, o);
    }
    int wid = threadIdx.x >> 5, lane = threadIdx.x & 31;
    if (lane == 0) { sh[wid] = s; sh2[wid] = s2; }
    __syncthreads();
    if (threadIdx.x == 0) {
        float a = 0.f, a2 = 0.f;
        for (int i = 0; i < (int)(blockDim.x >> 5); i++) { a += sh[i]; a2 += sh2[i]; }
        sh[0] = a; sh2[0] = a2;
    }
    __syncthreads();
    float mu  = sh[0] * (1.0f / DIM);
    float var = sh2[0] * (1.0f / DIM) - mu * mu;
    float inv = rsqrtf(var + LN_EPS);
    float* o = g_normed + (size_t)row * DIM;
    for (int i = threadIdx.x; i < DIM; i += blockDim.x)
        o[i] = rtf((xr[i] - mu) * inv * w[i] + b[i]);
}

// ---------------- tiled transpose + tf32 rounding: in[R][C] -> out[C][R] ----------------
__global__ void transpose_k(const float* __restrict__ in, float* __restrict__ out,
                            int R, int C) {
    __shared__ float t[32][33];
    int c0 = blockIdx.x * 32, r0 = blockIdx.y * 32;
    int x = threadIdx.x, y = threadIdx.y;
#pragma unroll
    for (int j = 0; j < 32; j += 8)
        t[y + j][x] = in[(size_t)(r0 + y + j) * C + c0 + x];
    __syncthreads();
#pragma unroll
    for (int j = 0; j < 32; j += 8)
        out[(size_t)(c0 + y + j) * R + r0 + x] = rtf(t[x][y + j]);
}

// ---------------- exclusive group cumsum of lin_kv (tf32-rounded output) ----------------
__global__ void cumsum_kernel() {
    int p = blockIdx.x * blockDim.x + threadIdx.x;
    if (p >= NB * QK * HID) return;
    int b = p / (QK * HID);
    int off = p - b * (QK * HID);
    float acc = 0.f;
#pragma unroll
    for (int g = 0; g < NGPB; g++) {
        size_t idx = (size_t)(b * NGPB + g) * (QK * HID) + off;
        float t = g_linkv[idx];
        g_linkv[idx] = rtf(acc);
        acc += t;
    }
}

// ---------------- tf32 mma.sync GEMM, 128x128 CTA tile, K-chunk 32, LDSM fragments ----------------
// CFG 1: A=g_normed, B=g_WhT (x<32) / g_WqkT (x==32), M=16384, K=1024
//        epilogue: n0<2048 -> silu->g_vT (transposed); n0<4096 -> silu->g_gate;
//                  n0>=4096 -> qk heads: qq(tf32)/lq/qkh(tf32) + lkT transposed
// CFG 7: A=g_qq[z], B=g_qkh[z], M=256,N=256,K=128; epi: /G + T5 bias + relu^2 + mask -> g_attn
// CFG 4: A=g_vT[z], B=g_lkT[z], M=2048,N=128,K=256; *(1/256) -> g_linkv [e][d]
// CFG 5 (merged): acc = attn[z]@vT[z] (K=256) + lq[z]@linkv[z] (K=128);
//        epi: g_ao = rtf(acc * gate)
// CFG 6: A=g_ao, B=g_WoutT, M=16384,N=1024,K=2048; +bout+x -> out
#define STG     18432                       // one 128x32 operand stage (stride 36 floats)
#define GEMM_SMEM (4 * STG)                 // 73728: As0,Bs0,As1,Bs1 (epilogue reuses)

__device__ __forceinline__ uint32_t smem_u32(const void* p) {
    uint32_t a;
    asm("{ .reg .u64 t; cvta.to.shared.u64 t, %1; cvt.u32.u64 %0, t; }" : "=r"(a) : "l"(p));
    return a;
}
__device__ __forceinline__ void mma8(float* d, const uint32_t* a, const uint32_t* b) {
    asm volatile(
        "mma.sync.aligned.m16n8k8.row.col.f32.tf32.tf32.f32 "
        "{%0,%1,%2,%3}, {%4,%5,%6,%7}, {%8,%9}, {%0,%1,%2,%3};"
        : "+f"(d[0]), "+f"(d[1]), "+f"(d[2]), "+f"(d[3])
        : "r"(a[0]), "r"(a[1]), "r"(a[2]), "r"(a[3]), "r"(b[0]), "r"(b[1]));
}
__device__ __forceinline__ void ldsm4(uint32_t& r0, uint32_t& r1, uint32_t& r2, uint32_t& r3,
                                      uint32_t addr) {
    asm volatile("ldmatrix.sync.aligned.m8n8.x4.shared.b16 {%0,%1,%2,%3}, [%4];"
                 : "=r"(r0), "=r"(r1), "=r"(r2), "=r"(r3) : "r"(addr));
}

template <int CFG>
__global__ void __launch_bounds__(256)
gemm_tc(const float* __restrict__ pbias, const float* __restrict__ paux,
        float* __restrict__ pout,
        const float* __restrict__ pbias2, const float* __restrict__ pqkw,
        const float* __restrict__ pqkb) {
    constexpr int K  = (CFG == 1) ? 1024
                     : (CFG == 4) ? 256
                     : (CFG == 5 || CFG == 7) ? 128 : 2048;
    constexpr int NC = (CFG == 5) ? 12 : ((CFG == 1) ? 32 : K / 32);

    extern __shared__ char smem[];
    uint32_t sbase = smem_u32(smem);
    float* smf = (float*)smem;
    float* sb  = smf + 128 * 132;           // 256-entry T5 bias LUT (CFG7), free tail

    int tid = threadIdx.x, w = tid >> 5, lane = tid & 31;
    int grpL = lane >> 2, tig = lane & 3;
    int wm = w >> 2, wn = w & 3;            // 2 x 4 warp grid
    int z = blockIdx.z;
    int n0 = blockIdx.x * 128, m0 = blockIdx.y * 128;

    const float* Atile; const float* Btile;
    const float* A2tile = nullptr; const float* B2tile = nullptr;
    if (CFG == 1) {
        Atile = g_normed + (size_t)m0 * K;
        Btile = (n0 >= HV2) ? g_WqkT + (size_t)(n0 - HV2) * K
                            : g_WhT + (size_t)n0 * K;
    } else if (CFG == 7) {
        Atile = g_qq  + (size_t)z * G * QK + (size_t)m0 * QK;
        Btile = g_qkh + (size_t)z * G * QK + (size_t)n0 * QK;
    } else if (CFG == 4) {
        Atile = g_vT  + (size_t)z * HID * G + (size_t)m0 * G;
        Btile = g_lkT + (size_t)z * QK * G  + (size_t)n0 * G;
    } else if (CFG == 5) {
        Atile  = g_attn  + (size_t)z * G * G    + (size_t)m0 * G;    // K=256 phase
        Btile  = g_vT    + (size_t)z * HID * G  + (size_t)n0 * G;
        A2tile = g_lq    + (size_t)z * G * QK   + (size_t)m0 * QK;   // K=128 phase
        B2tile = g_linkv + (size_t)z * HID * QK + (size_t)n0 * QK;
    } else {
        Atile = g_ao    + (size_t)m0 * K;
        Btile = g_WoutT + (size_t)n0 * K;
    }

    float acc[4][4][4];
#pragma unroll
    for (int i = 0; i < 4; i++)
#pragma unroll
        for (int j = 0; j < 4; j++)
#pragma unroll
            for (int r = 0; r < 4; r++) acc[i][j][r] = 0.f;

    int ldr = tid >> 3, ldc = (tid & 7) * 4;          // global->smem mapping

    // ldmatrix lane-relative byte offsets
    int q = lane >> 3, rL = lane & 7;
    uint32_t laneA = (uint32_t)(((wm * 64 + (q & 1) * 8 + rL) * 36 + (q >> 1) * 4) * 4);
    uint32_t laneB = (uint32_t)(((wn * 32 + (q >> 1) * 8 + rL) * 36 + (q & 1) * 4) * 4) + STG;

    auto issue_chunk = [&](int cc, int st) {
        const float* Ap; const float* Bp; int ld;
        if (CFG == 5) {
            if (cc < 8) { Ap = Atile + cc * 32;        Bp = Btile + cc * 32;        ld = G;  }
            else        { Ap = A2tile + (cc - 8) * 32; Bp = B2tile + (cc - 8) * 32; ld = QK; }
        } else {
            Ap = Atile + cc * 32; Bp = Btile + cc * 32; ld = K;
        }
#pragma unroll
        for (int jj = 0; jj < 4; ++jj) {
            int r = ldr + jj * 32;
            uint32_t da = sbase + (uint32_t)(st * 2 * STG + (r * 36 + ldc) * 4);
            asm volatile("cp.async.cg.shared.global [%0], [%1], 16;"
                         :: "r"(da), "l"(Ap + (size_t)r * ld + ldc));
            asm volatile("cp.async.cg.shared.global [%0], [%1], 16;"
                         :: "r"(da + STG), "l"(Bp + (size_t)r * ld + ldc));
        }
    };

    issue_chunk(0, 0);
    asm volatile("cp.async.commit_group;");

    for (int c = 0; c < NC; ++c) {
        if (c + 1 < NC) {
            issue_chunk(c + 1, (c + 1) & 1);
            asm volatile("cp.async.commit_group;");
            asm volatile("cp.async.wait_group 1;");
        } else {
            asm volatile("cp.async.wait_group 0;");
        }
        __syncthreads();

        uint32_t abase = sbase + (uint32_t)((c & 1) * 2 * STG) + laneA;
        uint32_t bbase = sbase + (uint32_t)((c & 1) * 2 * STG) + laneB;
#pragma unroll
        for (int k8 = 0; k8 < 4; ++k8) {
            uint32_t af[4][4], bf[4][2];
#pragma unroll
            for (int i = 0; i < 4; ++i)
                ldsm4(af[i][0], af[i][1], af[i][2], af[i][3],
                      abase + (uint32_t)(i * 2304 + k8 * 32));
            ldsm4(bf[0][0], bf[0][1], bf[1][0], bf[1][1], bbase + (uint32_t)(k8 * 32));
            ldsm4(bf[2][0], bf[2][1], bf[3][0], bf[3][1],
                  bbase + (uint32_t)(2304 + k8 * 32));
#pragma unroll
            for (int i = 0; i < 4; ++i)
#pragma unroll
                for (int j = 0; j < 4; ++j)
                    mma8(acc[i][j], af[i], bf[j]);
        }
        __syncthreads();
    }

    // ---- stage accumulators into smem [128][132]; CFG7 also builds bias LUT ----
    if (CFG == 7) {
        int n = tid;
        int bucket;
        if (n <= 0)      bucket = 0;
        else if (n < 16) bucket = n;
        else {
            bucket = 16 + (int)(logf((float)n * (1.0f / 16.0f)) * 0.48089834696298783f * 16.0f);
            if (bucket > 31) bucket = 31;
        }
        sb[tid] = paux[bucket] * 11.313708498984761f;   // * sqrt(128)
    }
#pragma unroll
    for (int i = 0; i < 4; ++i) {
#pragma unroll
        for (int j = 0; j < 4; ++j) {
            int row = wm * 64 + i * 16 + grpL;
            int col = wn * 32 + j * 8 + tig * 2;
            smf[row * 132 + col]           = acc[i][j][0];
            smf[row * 132 + col + 1]       = acc[i][j][1];
            smf[(row + 8) * 132 + col]     = acc[i][j][2];
            smf[(row + 8) * 132 + col + 1] = acc[i][j][3];
        }
    }
    __syncthreads();

    // ---- epilogue / global write ----
    if (CFG == 1 && n0 < HID) {
        // v branch: write transposed into g_vT[grp][gn][t] (tf32: GEMM operand)
        int grp = m0 >> 8, tg0 = m0 & 255;
#pragma unroll
        for (int it = 0; it < 16; ++it) {
            int cc = it * 8 + w;
            int gn = n0 + cc;
            float bias = pbias[gn];
            int t = lane * 4;
            float4 o;
            o.x = rtf(silu(smf[(t + 0) * 132 + cc] + bias));
            o.y = rtf(silu(smf[(t + 1) * 132 + cc] + bias));
            o.z = rtf(silu(smf[(t + 2) * 132 + cc] + bias));
            o.w = rtf(silu(smf[(t + 3) * 132 + cc] + bias));
            *(float4*)&g_vT[((size_t)grp * HID + gn) * G + tg0 + t] = o;
        }
        return;
    }
    if (CFG == 1 && n0 >= HV2) {
        // qk heads: s = silu(acc + bqk); qq/qkh now tf32 (CFG7 operands), lq tf32, lkT transposed
        int grp = m0 >> 8, tg0 = m0 & 255;
#pragma unroll
        for (int it = 0; it < 16; ++it) {
            int idx = tid + it * 256;
            int r = idx >> 5, c4 = (idx & 31) * 4;
            int tok = m0 + r;
            float4 bq = *(const float4*)&pbias2[c4];
            float4 s;
            s.x = silu(smf[r * 132 + c4 + 0] + bq.x);
            s.y = silu(smf[r * 132 + c4 + 1] + bq.y);
            s.z = silu(smf[r * 132 + c4 + 2] + bq.z);
            s.w = silu(smf[r * 132 + c4 + 3] + bq.w);
            smf[r * 132 + c4 + 0] = s.x; smf[r * 132 + c4 + 1] = s.y;
            smf[r * 132 + c4 + 2] = s.z; smf[r * 132 + c4 + 3] = s.w;
            float4 w0 = *(const float4*)&pqkw[c4];
            float4 b0 = *(const float4*)&pqkb[c4];
            float4 o0;
            o0.x = rtf(s.x * w0.x + b0.x); o0.y = rtf(s.y * w0.y + b0.y);
            o0.z = rtf(s.z * w0.z + b0.z); o0.w = rtf(s.w * w0.w + b0.w);
            *(float4*)&g_qq[(size_t)tok * QK + c4] = o0;
            float4 w1 = *(const float4*)&pqkw[QK + c4];
            float4 b1 = *(const float4*)&pqkb[QK + c4];
            float4 o1;
            o1.x = rtf(s.x * w1.x + b1.x); o1.y = rtf(s.y * w1.y + b1.y);
            o1.z = rtf(s.z * w1.z + b1.z); o1.w = rtf(s.w * w1.w + b1.w);
            *(float4*)&g_lq[(size_t)tok * QK + c4] = o1;
            float4 w2 = *(const float4*)&pqkw[2 * QK + c4];
            float4 b2 = *(const float4*)&pqkb[2 * QK + c4];
            float4 o2;
            o2.x = rtf(s.x * w2.x + b2.x); o2.y = rtf(s.y * w2.y + b2.y);
            o2.z = rtf(s.z * w2.z + b2.z); o2.w = rtf(s.w * w2.w + b2.w);
            *(float4*)&g_qkh[(size_t)tok * QK + c4] = o2;
        }
        __syncthreads();
#pragma unroll
        for (int it = 0; it < 16; ++it) {
            int cc = it * 8 + w;
            float w3 = pqkw[3 * QK + cc], b3 = pqkb[3 * QK + cc];
            int t = lane * 4;
            float4 o;
            o.x = rtf(smf[(t + 0) * 132 + cc] * w3 + b3);
            o.y = rtf(smf[(t + 1) * 132 + cc] * w3 + b3);
            o.z = rtf(smf[(t + 2) * 132 + cc] * w3 + b3);
            o.w = rtf(smf[(t + 3) * 132 + cc] * w3 + b3);
            *(float4*)&g_lkT[((size_t)grp * QK + cc) * G + tg0 + t] = o;
        }
        return;
    }
#pragma unroll
    for (int it = 0; it < 16; ++it) {
        int idx = tid + it * 256;              // 4096 float4 slots
        int r = idx >> 5, c4 = (idx & 31) * 4;
        int gm = m0 + r, gn = n0 + c4;
        float v0 = smf[r * 132 + c4 + 0];
        float v1 = smf[r * 132 + c4 + 1];
        float v2 = smf[r * 132 + c4 + 2];
        float v3 = smf[r * 132 + c4 + 3];
        if (CFG == 1) {                        // gate branch (2048 <= n0 < 4096)
            float4 o;
            o.x = silu(v0 + pbias[gn + 0]); o.y = silu(v1 + pbias[gn + 1]);
            o.z = silu(v2 + pbias[gn + 2]); o.w = silu(v3 + pbias[gn + 3]);
            *(float4*)&g_gate[(size_t)gm * HID + (gn - HID)] = o;
        } else if (CFG == 7) {                 // attention scores
            float o4[4] = {v0, v1, v2, v3};
            float4 o;
#pragma unroll
            for (int jj = 0; jj < 4; ++jj) {
                int d = gm - (gn + jj);
                float a = 0.f;
                if (d >= 0) {
                    float sim = o4[jj] * (1.0f / G) + sb[d];
                    a = sim > 0.f ? sim * sim : 0.f;
                }
                (&o.x)[jj] = rtf(a);
            }
            *(float4*)&g_attn[(size_t)z * (G * G) + (size_t)gm * G + gn] = o;
        } else if (CFG == 4) {                 // cumsum rounds later
            float4 o = make_float4(v0 * (1.0f / G), v1 * (1.0f / G),
                                   v2 * (1.0f / G), v3 * (1.0f / G));
            *(float4*)&g_linkv[((size_t)z * HID + gm) * QK + gn] = o;
        } else if (CFG == 5) {                 // merged quad+lin, gated
            size_t i0 = ((size_t)z * G + gm) * HID + gn;
            float4 gt = *(const float4*)&g_gate[i0];
            float4 o;
            o.x = rtf(v0 * gt.x); o.y = rtf(v1 * gt.y);
            o.z = rtf(v2 * gt.z); o.w = rtf(v3 * gt.w);
            *(float4*)&g_ao[i0] = o;
        } else {                               // CFG 6
            size_t i0 = (size_t)gm * DIM + gn;
            float4 xr = *(const float4*)&paux[i0];
            float4 o;
            o.x = v0 + pbias[gn + 0] + xr.x; o.y = v1 + pbias[gn + 1] + xr.y;
            o.z = v2 + pbias[gn + 2] + xr.z; o.w = v3 + pbias[gn + 3] + xr.w;
            *(float4*)&pout[i0] = o;
        }
    }
}

// ---------------- launch ----------------
extern "C" void kernel_launch(void* const* d_in, const int* in_sizes, int n_in,
                              void* d_out, int out_size) {
    const float* x    = (const float*)d_in[0];
    const float* ln_w = (const float*)d_in[1];
    const float* ln_b = (const float*)d_in[2];
    const float* Wh   = (const float*)d_in[3];
    const float* bh   = (const float*)d_in[4];
    const float* Wqk  = (const float*)d_in[5];
    const float* bqk  = (const float*)d_in[6];
    const float* qk_w = (const float*)d_in[7];
    const float* qk_b = (const float*)d_in[8];
    const float* rel  = (const float*)d_in[9];
    const float* Wout = (const float*)d_in[10];
    const float* bout = (const float*)d_in[11];
    float* out = (float*)d_out;

    cudaFuncSetAttribute(gemm_tc<1>, cudaFuncAttributeMaxDynamicSharedMemorySize, GEMM_SMEM);
    cudaFuncSetAttribute(gemm_tc<4>, cudaFuncAttributeMaxDynamicSharedMemorySize, GEMM_SMEM);
    cudaFuncSetAttribute(gemm_tc<5>, cudaFuncAttributeMaxDynamicSharedMemorySize, GEMM_SMEM);
    cudaFuncSetAttribute(gemm_tc<6>, cudaFuncAttributeMaxDynamicSharedMemorySize, GEMM_SMEM);
    cudaFuncSetAttribute(gemm_tc<7>, cudaFuncAttributeMaxDynamicSharedMemorySize, GEMM_SMEM);

    float* WhT;   cudaGetSymbolAddress((void**)&WhT,   g_WhT);
    float* WqkT;  cudaGetSymbolAddress((void**)&WqkT,  g_WqkT);
    float* WoutT; cudaGetSymbolAddress((void**)&WoutT, g_WoutT);

    // weight transposes (K-major B operands, tf32-rounded)
    transpose_k<<<dim3(HV2 / 32, DIM / 32), dim3(32, 8)>>>(Wh,   WhT,   DIM, HV2);
    transpose_k<<<dim3(QK  / 32, DIM / 32), dim3(32, 8)>>>(Wqk,  WqkT,  DIM, QK);
    transpose_k<<<dim3(DIM / 32, HID / 32), dim3(32, 8)>>>(Wout, WoutT, HID, DIM);

    // 1) LayerNorm
    ln_kernel<<<NTOK, 256>>>(x, ln_w, ln_b);

    // 2) fused: hv = silu(normed @ [Wh|Wqk] + [bh|bqk]) -> vT + gate + qk heads
    gemm_tc<1><<<dim3(HV2 / 128 + 1, NTOK / 128, 1), 256, GEMM_SMEM>>>(
        bh, nullptr, nullptr, bqk, qk_w, qk_b);

    // 3) attn scores (tensorized): relu^2(qq@qkh^T / G + T5 bias), causal
    gemm_tc<7><<<dim3(G / 128, G / 128, NGRP), 256, GEMM_SMEM>>>(
        nullptr, rel, nullptr, nullptr, nullptr, nullptr);

    // 4) lin_kv = v^T @ lin_k / g   -> [e][d]
    gemm_tc<4><<<dim3(1, HID / 128, NGRP), 256, GEMM_SMEM>>>(
        nullptr, nullptr, nullptr, nullptr, nullptr, nullptr);

    // 5) exclusive group cumsum
    cumsum_kernel<<<(NB * QK * HID) / 256, 256>>>();

    // 6) merged: ao = gate * (attn@v + lin_q@lin_kv)
    gemm_tc<5><<<dim3(HID / 128, G / 128, NGRP), 256, GEMM_SMEM>>>(
        nullptr, nullptr, nullptr, nullptr, nullptr, nullptr);

    // 7) out = ao @ Wout + bout + x
    gemm_tc<6><<<dim3(DIM / 128, NTOK / 128, 1), 256, GEMM_SMEM>>>(
        bout, x, out, nullptr, nullptr, nullptr);
}